// round 8
// baseline (speedup 1.0000x reference)
#include <cuda_runtime.h>
#include <math.h>

// Problem constants
#define BB 16
#define CC 48
#define TT 96
#define PATCH 12
#define STEPS 7          // (T - PATCH) / PATCH
#define FF 64
#define TOPK 3
#define ALPHA 0.5f
#define EPS 1e-5f
#define NFEAT (CC*TT)    // 4608
#define CP (CC*PATCH)    // 576

// Scratch (allocation-free rule: __device__ globals)
__device__ float d_xn[BB*NFEAT];       // normalized input (B,C,T)
__device__ float d_resbuf[BB*CP];      // per-step residual (B,C,P)
__device__ float d_tbuf[BB*CP];        // per-step t (B,C,P)

__device__ __forceinline__ float gelu_exact(float v) {
    return 0.5f * v * (1.0f + erff(v * 0.70710678118654752f));
}

// ---------------------------------------------------------------------------
// Kernel 0: BatchNorm over batch dim for all C*T features; writes xn and the
// first patch (columns 0..11) directly into d_out.
// 4608 threads, one per feature. Two-pass mean/var in registers.
// ---------------------------------------------------------------------------
__global__ void bn0_kernel(const float* __restrict__ x,
                           const float* __restrict__ g0,
                           const float* __restrict__ b0,
                           float* __restrict__ out)
{
    int f = blockIdx.x * blockDim.x + threadIdx.x;
    if (f >= NFEAT) return;
    float v[BB];
    float sum = 0.f;
    #pragma unroll
    for (int b = 0; b < BB; b++) { v[b] = x[b*NFEAT + f]; sum += v[b]; }
    float mu = sum * (1.0f/BB);
    float var = 0.f;
    #pragma unroll
    for (int b = 0; b < BB; b++) { float d = v[b] - mu; var = fmaf(d, d, var); }
    var *= (1.0f/BB);
    float rs = rsqrtf(var + EPS);
    float g = g0[f], bb0 = b0[f];
    int t = f % TT;
    #pragma unroll
    for (int b = 0; b < BB; b++) {
        float y = (v[b] - mu) * rs * g + bb0;
        d_xn[b*NFEAT + f] = y;
        if (t < PATCH) out[b*NFEAT + f] = y;   // first patch goes straight to output
    }
}

// ---------------------------------------------------------------------------
// Step kernel A: per channel c — BN1(prev) -> Wagg matmul + gelu -> +xw ->
// BN2 -> t. prev is read from d_out columns [12*s, 12*s+12).
// grid = 48 blocks, 192 threads (b = tid/12, p = tid%12).
// ---------------------------------------------------------------------------
__global__ void stepA_kernel(float* __restrict__ out,
                             const float* __restrict__ g1, const float* __restrict__ b1,
                             const float* __restrict__ g2, const float* __restrict__ b2,
                             const float* __restrict__ Wagg, const float* __restrict__ bagg,
                             int s)
{
    int c = blockIdx.x;
    int tid = threadIdx.x;           // 0..191
    int b = tid / PATCH;
    int p = tid % PATCH;

    __shared__ float sV[BB][PATCH];
    __shared__ float sMu[PATCH], sRs[PATCH];
    __shared__ float sR[BB][PATCH];

    // prev value
    sV[b][p] = out[b*NFEAT + c*TT + 12*s + p];
    __syncthreads();

    if (tid < PATCH) {
        float sum = 0.f;
        #pragma unroll
        for (int x = 0; x < BB; x++) sum += sV[x][tid];
        float mu = sum * (1.0f/BB);
        float var = 0.f;
        #pragma unroll
        for (int x = 0; x < BB; x++) { float d = sV[x][tid] - mu; var = fmaf(d, d, var); }
        var *= (1.0f/BB);
        sMu[tid] = mu;
        sRs[tid] = rsqrtf(var + EPS);
    }
    __syncthreads();

    float bnv = (sV[b][p] - sMu[p]) * sRs[p] * g1[c*PATCH + p] + b1[c*PATCH + p];
    sV[b][p] = bnv;   // each thread overwrites only its own element; readers synced below
    __syncthreads();

    // inp[b][q] = gelu(sum_p bn[b][p] * Wagg[q][p] + bagg[q]); here q == p role
    float acc = bagg[p];
    #pragma unroll
    for (int pp = 0; pp < PATCH; pp++)
        acc = fmaf(sV[b][pp], Wagg[p*PATCH + pp], acc);
    float inp = gelu_exact(acc);
    float res = inp + d_xn[b*NFEAT + c*TT + 12 + 12*s + p];
    sR[b][p] = res;
    d_resbuf[b*CP + c*PATCH + p] = res;
    __syncthreads();

    if (tid < PATCH) {
        float sum = 0.f;
        #pragma unroll
        for (int x = 0; x < BB; x++) sum += sR[x][tid];
        float mu = sum * (1.0f/BB);
        float var = 0.f;
        #pragma unroll
        for (int x = 0; x < BB; x++) { float d = sR[x][tid] - mu; var = fmaf(d, d, var); }
        var *= (1.0f/BB);
        sMu[tid] = mu;
        sRs[tid] = rsqrtf(var + EPS);
    }
    __syncthreads();

    float tv = (sR[b][p] - sMu[p]) * sRs[p] * g2[c*PATCH + p] + b2[c*PATCH + p];
    d_tbuf[b*CP + c*PATCH + p] = tv;
}

// ---------------------------------------------------------------------------
// Step kernel B: edge MLP + top-3 + softmax + message aggregation.
// grid = 192 (b,p) * SPLIT row-segments; 192 threads/block.
// Each block computes a 16x48 slab of the e-matrix, then does top-k/softmax
// for its 16 rows and writes output column 12 + 12*s + p.
// ---------------------------------------------------------------------------
#define SPLIT 3
#define ROWS_PER_BLK (CC / SPLIT)   // 16

__global__ void stepB_kernel(float* __restrict__ out,
                             const float* __restrict__ W1, const float* __restrict__ bm1,
                             const float* __restrict__ W2, const float* __restrict__ bm2,
                             const float* __restrict__ wmsg, const float* __restrict__ bmsg,
                             int s)
{
    int blk = blockIdx.x;            // 0..575
    int bp  = blk / SPLIT;
    int seg = blk % SPLIT;
    int b = bp / PATCH;
    int p = bp % PATCH;
    int tid = threadIdx.x;           // 0..191

    __shared__ float  sT[CC], sMsg[CC], sRes[CC];
    __shared__ float4 sW[FF];
    __shared__ float  sE[ROWS_PER_BLK * CC];   // 768

    if (tid < CC) {
        float tv = d_tbuf[b*CP + tid*PATCH + p];
        sT[tid]   = tv;
        sMsg[tid] = tv * wmsg[0] + bmsg[0];
        sRes[tid] = d_resbuf[b*CP + tid*PATCH + p];
    }
    if (tid >= 64 && tid < 128) {
        int f = tid - 64;
        sW[f] = make_float4(W1[2*f], W1[2*f+1], bm1[f], W2[f]);
    }
    __syncthreads();

    float bm2v = bm2[0];

    // 768 pairs / 192 threads = 4 pairs each; 4-way ILP on the erff chains.
    float zi[4], zj[4], acc[4];
    #pragma unroll
    for (int u = 0; u < 4; u++) {
        int k = tid + u*192;
        int il = k / CC;
        int j  = k % CC;
        zi[u] = sT[seg*ROWS_PER_BLK + il];
        zj[u] = sT[j];
        acc[u] = bm2v;
    }
    #pragma unroll 8
    for (int f = 0; f < FF; f++) {
        float4 w = sW[f];
        #pragma unroll
        for (int u = 0; u < 4; u++) {
            float a = fmaf(w.x, zi[u], fmaf(w.y, zj[u], w.z));
            float g = 0.5f * a * (1.0f + erff(a * 0.70710678118654752f));
            acc[u] = fmaf(w.w, g, acc[u]);
        }
    }
    #pragma unroll
    for (int u = 0; u < 4; u++) sE[tid + u*192] = acc[u];
    __syncthreads();

    // top-3 + softmax + aggregate: one thread per row
    if (tid < ROWS_PER_BLK) {
        int i = seg*ROWS_PER_BLK + tid;
        const float* row = &sE[tid*CC];
        float v0 = -1e30f, v1 = -1e30f, v2 = -1e30f;
        int   i0 = 0,      i1 = 0,      i2 = 0;
        #pragma unroll 4
        for (int j = 0; j < CC; j++) {
            float e = row[j];
            if (e > v0)      { v2=v1; i2=i1; v1=v0; i1=i0; v0=e; i0=j; }
            else if (e > v1) { v2=v1; i2=i1; v1=e;  i1=j; }
            else if (e > v2) { v2=e;  i2=j; }
        }
        // softmax over the 3 kept values (masked rest underflows to exactly 0)
        float e1 = expf(v1 - v0), e2 = expf(v2 - v0);
        float inv = 1.0f / (1.0f + e1 + e2);
        float zn = (sMsg[i0] + e1*sMsg[i1] + e2*sMsg[i2]) * inv;
        float o = sRes[i] + ALPHA * zn;
        out[b*NFEAT + i*TT + 12 + 12*s + p] = o;   // also serves as prev for step s+1
    }
}

// ---------------------------------------------------------------------------
extern "C" void kernel_launch(void* const* d_in, const int* in_sizes, int n_in,
                              void* d_out, int out_size)
{
    const float* x    = (const float*)d_in[0];
    const float* g0   = (const float*)d_in[1];
    const float* b0   = (const float*)d_in[2];
    const float* g1   = (const float*)d_in[3];
    const float* b1   = (const float*)d_in[4];
    const float* g2   = (const float*)d_in[5];
    const float* b2   = (const float*)d_in[6];
    const float* Wagg = (const float*)d_in[7];
    const float* bagg = (const float*)d_in[8];
    const float* W1   = (const float*)d_in[9];
    const float* bm1  = (const float*)d_in[10];
    const float* W2   = (const float*)d_in[11];
    const float* bm2  = (const float*)d_in[12];
    const float* wmsg = (const float*)d_in[13];
    const float* bmsg = (const float*)d_in[14];
    float* out = (float*)d_out;

    bn0_kernel<<<(NFEAT + 255)/256, 256>>>(x, g0, b0, out);

    for (int s = 0; s < STEPS; s++) {
        stepA_kernel<<<CC, BB*PATCH>>>(out, g1, b1, g2, b2, Wagg, bagg, s);
        stepB_kernel<<<BB*PATCH*SPLIT, 192>>>(out, W1, bm1, W2, bm2, wmsg, bmsg, s);
    }
}